// round 14
// baseline (speedup 1.0000x reference)
#include <cuda_runtime.h>
#include <cuda_bf16.h>
#include <math.h>
#include <stdint.h>

#define BSZ  4
#define NSEQ 512
#define DIM  128
#define MROWS (BSZ * NSEQ)      // 2048
#define KSPLIT 4

// ---- scratch (__device__ globals; no cudaMalloc allowed) -------------------
__device__ float g_q   [MROWS * DIM];
__device__ float g_ek  [MROWS * DIM];
__device__ float g_vraw[MROWS * DIM];
__device__ float g_pnum[KSPLIT * MROWS * DIM];
__device__ float g_pden[KSPLIT * MROWS * DIM];
__device__ int   g_ctr [64];            // per-output-tile arrival counters (zero-init)

// bf16 hi/lo split operands
__device__ uint4 g_xh   [MROWS * DIM / 8];
__device__ uint4 g_xl   [MROWS * DIM / 8];
__device__ uint4 g_wch  [3 * DIM * DIM / 8];
__device__ uint4 g_wcl  [3 * DIM * DIM / 8];
__device__ uint4 g_wh   [NSEQ * NSEQ / 8];
__device__ uint4 g_wl   [NSEQ * NSEQ / 8];
__device__ uint4 g_ekvTh[BSZ * DIM * NSEQ / 8];
__device__ uint4 g_ekvTl[BSZ * DIM * NSEQ / 8];
__device__ uint4 g_ekTh [BSZ * DIM * NSEQ / 8];
__device__ uint4 g_ekTl [BSZ * DIM * NSEQ / 8];

// ---------------------------------------------------------------------------
__device__ __forceinline__ uint32_t smem_u32(const void* p) {
    uint32_t a;
    asm("{ .reg .u64 t; cvta.to.shared.u64 t, %1; cvt.u32.u64 %0, t; }"
        : "=r"(a) : "l"(p));
    return a;
}
#define LDSM_X4(r0, r1, r2, r3, addr) \
    asm volatile("ldmatrix.sync.aligned.m8n8.x4.shared.b16 {%0,%1,%2,%3}, [%4];" \
        : "=r"(r0), "=r"(r1), "=r"(r2), "=r"(r3) : "r"(addr))

#define MMA16816(d, a, b0, b1) \
    asm volatile("mma.sync.aligned.m16n8k16.row.col.f32.bf16.bf16.f32 " \
        "{%0,%1,%2,%3}, {%4,%5,%6,%7}, {%8,%9}, {%0,%1,%2,%3};" \
        : "+f"((d)[0]), "+f"((d)[1]), "+f"((d)[2]), "+f"((d)[3]) \
        : "r"((a)[0]), "r"((a)[1]), "r"((a)[2]), "r"((a)[3]), \
          "r"(b0), "r"(b1))

__device__ __forceinline__ void cp16(uint32_t saddr, const void* gptr) {
    asm volatile("cp.async.cg.shared.global [%0], [%1], 16;"
                 :: "r"(saddr), "l"(gptr));
}
__device__ __forceinline__ void cp_commit() {
    asm volatile("cp.async.commit_group;" ::: "memory");
}
__device__ __forceinline__ void cp_wait0() {
    asm volatile("cp.async.wait_group 0;" ::: "memory");
}

__device__ __forceinline__ void bsplit(float x, unsigned short& h, unsigned short& l) {
    __nv_bfloat16 hb = __float2bfloat16(x);
    __nv_bfloat16 lb = __float2bfloat16(x - __bfloat162float(hb));
    h = __bfloat16_as_ushort(hb);
    l = __bfloat16_as_ushort(lb);
}

// geometry
#define RSTRIDE 80
#define PSA_HI 0
#define PSA_LO 5120
#define PSB_HI 10240
#define PSB_LO 15360
#define PBUFSZ 20480
#define ASA_HI 0
#define ASA_LO 5120
#define ASB_HI 10240
#define ASB_LO 20480
#define ABUFSZ 30720
#define AFT_SMEM (2 * ABUFSZ)   // 61440

// ---------------------------------------------------------------------------
// Kernel 0: merged input prep — x split, Wcat split, exp(pos_bias) split.
// items: x 131072 + Wcat 24576 + pos_bias 131072 = 286720 float2 -> 1120 blks
// ---------------------------------------------------------------------------
__global__ __launch_bounds__(256)
void prep_inputs_kernel(const float* __restrict__ x,
                        const float* __restrict__ Wq,
                        const float* __restrict__ Wk,
                        const float* __restrict__ Wv,
                        const float* __restrict__ pos_bias)
{
    int i = blockIdx.x * 256 + threadIdx.x;
    if (i < MROWS * DIM / 2) {                       // x
        float2 p = reinterpret_cast<const float2*>(x)[i];
        unsigned short h0, l0, h1, l1;
        bsplit(p.x, h0, l0); bsplit(p.y, h1, l1);
        reinterpret_cast<uint32_t*>(g_xh)[i] = ((uint32_t)h1 << 16) | h0;
        reinterpret_cast<uint32_t*>(g_xl)[i] = ((uint32_t)l1 << 16) | l0;
    } else if (i < MROWS * DIM / 2 + 3 * DIM * DIM / 2) {   // Wcat
        int j = i - MROWS * DIM / 2;
        int row = j >> 6, c2 = j & 63;
        int m = row >> 7, rr = row & 127;
        const float* W = (m == 0) ? Wq : (m == 1) ? Wk : Wv;
        float2 p = reinterpret_cast<const float2*>(W + rr * DIM)[c2];
        unsigned short h0, l0, h1, l1;
        bsplit(p.x, h0, l0); bsplit(p.y, h1, l1);
        reinterpret_cast<uint32_t*>(g_wch)[j] = ((uint32_t)h1 << 16) | h0;
        reinterpret_cast<uint32_t*>(g_wcl)[j] = ((uint32_t)l1 << 16) | l0;
    } else {                                          // exp(pos_bias)
        int j = i - (MROWS * DIM / 2 + 3 * DIM * DIM / 2);
        float2 p = reinterpret_cast<const float2*>(pos_bias)[j];
        float e0 = __expf(p.x), e1 = __expf(p.y);
        unsigned short h0, l0, h1, l1;
        bsplit(e0, h0, l0); bsplit(e1, h1, l1);
        reinterpret_cast<uint32_t*>(g_wh)[j] = ((uint32_t)h1 << 16) | h0;
        reinterpret_cast<uint32_t*>(g_wl)[j] = ((uint32_t)l1 << 16) | l0;
    }
}

// ---------------------------------------------------------------------------
// Kernel 1: projections on mma.sync (structure unchanged; __expf epilogue)
// ---------------------------------------------------------------------------
__global__ __launch_bounds__(256)
void proj_mma_kernel(const float* __restrict__ bq,
                     const float* __restrict__ bk,
                     const float* __restrict__ bv)
{
    __shared__ __align__(16) char sm[2 * PBUFSZ];
    const uint32_t smem = smem_u32(sm);

    const int tid  = threadIdx.x;
    const int wid  = tid >> 5, lane = tid & 31;
    const int et   = blockIdx.x;
    const int rt   = blockIdx.y;
    const int m    = et >> 1;
    const int r0   = rt * 64;
    const int e0   = et * 64;

    const float* __restrict__ bias = (m == 0) ? bq : (m == 1) ? bk : bv;
    float* __restrict__ outp       = (m == 0) ? g_q : (m == 1) ? g_ek : g_vraw;

    const int srow = tid >> 2, sseg = tid & 3;
    const uint32_t soff = (uint32_t)(srow * RSTRIDE + sseg * 16);
    const int a_g = (r0 + srow) * 16 + sseg;
    const int b_g = (e0 + srow) * 16 + sseg;

    const int wm = wid & 1, wn = wid >> 1;
    const int r  = lane & 7, sel = lane >> 3;

    uint32_t aoff[2][2], boff[2];
    #pragma unroll
    for (int mt = 0; mt < 2; ++mt)
        #pragma unroll
        for (int ks = 0; ks < 2; ++ks) {
            int row = wm * 32 + mt * 16 + r + (sel & 1) * 8;
            aoff[mt][ks] = smem + PSA_HI + row * RSTRIDE + ((sel >> 1) * 16) + ks * 32;
        }
    #pragma unroll
    for (int ks = 0; ks < 2; ++ks) {
        int row = wn * 16 + r + (sel >> 1) * 8;
        boff[ks] = smem + PSB_HI + row * RSTRIDE + ((sel & 1) * 16) + ks * 32;
    }

    float acc[2][2][4] = {};

    uint4 pAh = g_xh[a_g], pAl = g_xl[a_g], pBh = g_wch[b_g], pBl = g_wcl[b_g];
    *reinterpret_cast<uint4*>(sm + PSA_HI + soff) = pAh;
    *reinterpret_cast<uint4*>(sm + PSA_LO + soff) = pAl;
    *reinterpret_cast<uint4*>(sm + PSB_HI + soff) = pBh;
    *reinterpret_cast<uint4*>(sm + PSB_LO + soff) = pBl;
    __syncthreads();

    for (int c = 0; c < 4; ++c) {
        const uint32_t bo = (uint32_t)(c & 1) * PBUFSZ;
        if (c < 3) {
            int gi = (c + 1) * 4;
            pAh = g_xh[a_g + gi];  pAl = g_xl[a_g + gi];
            pBh = g_wch[b_g + gi]; pBl = g_wcl[b_g + gi];
        }
        #pragma unroll
        for (int ks = 0; ks < 2; ++ks) {
            uint32_t aH[2][4], aL[2][4], bH[4], bL[4];
            LDSM_X4(aH[0][0], aH[0][1], aH[0][2], aH[0][3], aoff[0][ks] + bo);
            LDSM_X4(aH[1][0], aH[1][1], aH[1][2], aH[1][3], aoff[1][ks] + bo);
            LDSM_X4(aL[0][0], aL[0][1], aL[0][2], aL[0][3], aoff[0][ks] + bo + PSA_LO);
            LDSM_X4(aL[1][0], aL[1][1], aL[1][2], aL[1][3], aoff[1][ks] + bo + PSA_LO);
            LDSM_X4(bH[0], bH[1], bH[2], bH[3], boff[ks] + bo);
            LDSM_X4(bL[0], bL[1], bL[2], bL[3], boff[ks] + bo + PSA_LO);
            #pragma unroll
            for (int mt = 0; mt < 2; ++mt)
                #pragma unroll
                for (int nt = 0; nt < 2; ++nt) {
                    MMA16816(acc[mt][nt], aH[mt], bH[nt * 2], bH[nt * 2 + 1]);
                    MMA16816(acc[mt][nt], aH[mt], bL[nt * 2], bL[nt * 2 + 1]);
                    MMA16816(acc[mt][nt], aL[mt], bH[nt * 2], bH[nt * 2 + 1]);
                }
        }
        if (c < 3) {
            const uint32_t nb = (uint32_t)((c + 1) & 1) * PBUFSZ;
            *reinterpret_cast<uint4*>(sm + nb + PSA_HI + soff) = pAh;
            *reinterpret_cast<uint4*>(sm + nb + PSA_LO + soff) = pAl;
            *reinterpret_cast<uint4*>(sm + nb + PSB_HI + soff) = pBh;
            *reinterpret_cast<uint4*>(sm + nb + PSB_LO + soff) = pBl;
        }
        __syncthreads();
    }

    const int g  = lane >> 2;
    const int t2 = (lane & 3) * 2;
    #pragma unroll
    for (int mt = 0; mt < 2; ++mt)
        #pragma unroll
        for (int nt = 0; nt < 2; ++nt) {
            int trow = r0 + wm * 32 + mt * 16 + g;
            int ew   = (et & 1) * 64 + wn * 16 + nt * 8 + t2;
            float b0 = bias[ew], b1 = bias[ew + 1];
            #pragma unroll
            for (int hh = 0; hh < 2; ++hh) {
                float v0 = acc[mt][nt][hh * 2 + 0] + b0;
                float v1 = acc[mt][nt][hh * 2 + 1] + b1;
                if (m == 0)      { v0 = 1.0f / (1.0f + __expf(-v0)); v1 = 1.0f / (1.0f + __expf(-v1)); }
                else if (m == 1) { v0 = __expf(v0); v1 = __expf(v1); }
                *reinterpret_cast<float2*>(&outp[(size_t)(trow + hh * 8) * DIM + ew]) =
                    make_float2(v0, v1);
            }
        }
}

// ---------------------------------------------------------------------------
// Kernel 2: transpose-split ek/ekv -> [b][d][j] bf16 hi/lo. 256 blocks.
// ---------------------------------------------------------------------------
__global__ __launch_bounds__(256)
void prep_t_kernel()
{
    __shared__ float s_ek[32][33], s_v[32][33];
    const int tid = threadIdx.x;
    const int bx = blockIdx.x;
    const int jt = bx & 15, dt = (bx >> 4) & 3, b = bx >> 6;
    const int j0 = jt * 32, d0 = dt * 32;

    const float* __restrict__ ekp = g_ek   + b * NSEQ * DIM;
    const float* __restrict__ vp  = g_vraw + b * NSEQ * DIM;

    for (int i = tid; i < 1024; i += 256) {
        int jj = i >> 5, dd = i & 31;
        s_ek[jj][dd] = ekp[(j0 + jj) * DIM + d0 + dd];
        s_v [jj][dd] = vp [(j0 + jj) * DIM + d0 + dd];
    }
    __syncthreads();

    for (int i = tid; i < 512; i += 256) {
        int dd = i >> 4, jj = (i & 15) * 2;
        float ek0 = s_ek[jj][dd],     ek1 = s_ek[jj + 1][dd];
        float v0  = s_v [jj][dd],     v1  = s_v [jj + 1][dd];
        float ekv0 = ek0 * v0, ekv1 = ek1 * v1;
        unsigned short kh0, kl0, kh1, kl1, vh0, vl0, vh1, vl1;
        bsplit(ek0,  kh0, kl0);  bsplit(ek1,  kh1, kl1);
        bsplit(ekv0, vh0, vl0);  bsplit(ekv1, vh1, vl1);
        uint32_t u32i = (((b * DIM + d0 + dd) * NSEQ) + j0 + jj) >> 1;
        reinterpret_cast<uint32_t*>(g_ekTh )[u32i] = ((uint32_t)kh1 << 16) | kh0;
        reinterpret_cast<uint32_t*>(g_ekTl )[u32i] = ((uint32_t)kl1 << 16) | kl0;
        reinterpret_cast<uint32_t*>(g_ekvTh)[u32i] = ((uint32_t)vh1 << 16) | vh0;
        reinterpret_cast<uint32_t*>(g_ekvTl)[u32i] = ((uint32_t)vl1 << 16) | vl0;
    }
}

// ---------------------------------------------------------------------------
// Kernel 3: AFT core (mainloop unchanged from R11 design) + fused finalize.
// The last K-split block per output tile sums the 4 partials (fixed order,
// deterministic) and writes q * num / den.
// ---------------------------------------------------------------------------
__global__ __launch_bounds__(256)
void aft_mma_kernel(float* __restrict__ out)
{
    extern __shared__ __align__(16) char sm[];
    const uint32_t smem = smem_u32(sm);
    __shared__ int s_last;

    const int tid  = threadIdx.x;
    const int wid  = tid >> 5, lane = tid & 31;
    const int bx   = blockIdx.x;
    const int ksl  = bx & 3;
    const int b    = (bx >> 2) & 3;
    const int tt   = (bx >> 4) & 7;
    const int dh   = (bx >> 7) & 1;
    const int t0   = tt * 64;
    const int d0   = dh * 64;
    const int j0u4 = ksl * 16;

    const uint4* srcH[3];
    const uint4* srcL[3];
    uint32_t shOff[3], slOff[3];
    int gb[3];
    #pragma unroll
    for (int k = 0; k < 3; ++k) {
        int i = tid + k * 256;
        int row = i >> 2, seg = i & 3;
        if (row < 64) {
            srcH[k] = g_wh;  srcL[k] = g_wl;
            shOff[k] = ASA_HI + row * RSTRIDE + seg * 16;
            slOff[k] = ASA_LO + row * RSTRIDE + seg * 16;
            gb[k] = (t0 + row) * 64 + j0u4 + seg;
        } else {
            int n = row - 64;
            shOff[k] = ASB_HI + n * RSTRIDE + seg * 16;
            slOff[k] = ASB_LO + n * RSTRIDE + seg * 16;
            int dcol = (n < 64) ? (d0 + n) : (d0 + n - 64);
            srcH[k] = (n < 64) ? g_ekvTh : g_ekTh;
            srcL[k] = (n < 64) ? g_ekvTl : g_ekTl;
            gb[k] = (b * DIM + dcol) * 64 + j0u4 + seg;
        }
    }

    const int wm = wid & 1, wn = wid >> 1;
    const int r  = lane & 7, sel = lane >> 3;

    uint32_t aoff[2][2], boff[2][2];
    #pragma unroll
    for (int mt = 0; mt < 2; ++mt)
        #pragma unroll
        for (int ks = 0; ks < 2; ++ks) {
            int row = wm * 32 + mt * 16 + r + (sel & 1) * 8;
            aoff[mt][ks] = smem + ASA_HI + row * RSTRIDE + ((sel >> 1) * 16) + ks * 32;
        }
    #pragma unroll
    for (int ng = 0; ng < 2; ++ng)
        #pragma unroll
        for (int ks = 0; ks < 2; ++ks) {
            int row = wn * 32 + ng * 16 + r + (sel >> 1) * 8;
            boff[ng][ks] = smem + ASB_HI + row * RSTRIDE + ((sel & 1) * 16) + ks * 32;
        }

    float acc[2][4][4] = {};

    #pragma unroll
    for (int k = 0; k < 3; ++k) {
        cp16(smem + shOff[k], srcH[k] + gb[k]);
        cp16(smem + slOff[k], srcL[k] + gb[k]);
    }
    cp_commit();
    cp_wait0();
    __syncthreads();

    for (int c = 0; c < 4; ++c) {
        const uint32_t bo = (uint32_t)(c & 1) * ABUFSZ;
        if (c < 3) {
            const uint32_t nb = (uint32_t)((c + 1) & 1) * ABUFSZ;
            int gi = (c + 1) * 4;
            #pragma unroll
            for (int k = 0; k < 3; ++k) {
                cp16(smem + nb + shOff[k], srcH[k] + gb[k] + gi);
                cp16(smem + nb + slOff[k], srcL[k] + gb[k] + gi);
            }
            cp_commit();
        }

        #pragma unroll
        for (int ks = 0; ks < 2; ++ks) {
            uint32_t aH[2][4], aL[2][4], bH[2][4], bL[2][4];
            LDSM_X4(aH[0][0], aH[0][1], aH[0][2], aH[0][3], aoff[0][ks] + bo);
            LDSM_X4(aH[1][0], aH[1][1], aH[1][2], aH[1][3], aoff[1][ks] + bo);
            LDSM_X4(aL[0][0], aL[0][1], aL[0][2], aL[0][3], aoff[0][ks] + bo + 5120);
            LDSM_X4(aL[1][0], aL[1][1], aL[1][2], aL[1][3], aoff[1][ks] + bo + 5120);
            LDSM_X4(bH[0][0], bH[0][1], bH[0][2], bH[0][3], boff[0][ks] + bo);
            LDSM_X4(bH[1][0], bH[1][1], bH[1][2], bH[1][3], boff[1][ks] + bo);
            LDSM_X4(bL[0][0], bL[0][1], bL[0][2], bL[0][3], boff[0][ks] + bo + 10240);
            LDSM_X4(bL[1][0], bL[1][1], bL[1][2], bL[1][3], boff[1][ks] + bo + 10240);

            #pragma unroll
            for (int mt = 0; mt < 2; ++mt)
                #pragma unroll
                for (int ng = 0; ng < 2; ++ng)
                    #pragma unroll
                    for (int sub = 0; sub < 2; ++sub) {
                        int nt = ng * 2 + sub;
                        MMA16816(acc[mt][nt], aH[mt], bH[ng][sub * 2], bH[ng][sub * 2 + 1]);
                        MMA16816(acc[mt][nt], aH[mt], bL[ng][sub * 2], bL[ng][sub * 2 + 1]);
                        MMA16816(acc[mt][nt], aL[mt], bH[ng][sub * 2], bH[ng][sub * 2 + 1]);
                    }
        }
        cp_wait0();
        __syncthreads();
    }

    // ---- write partials ----
    const int g  = lane >> 2;
    const int t2 = (lane & 3) * 2;
    const size_t pbase = (size_t)(ksl * BSZ + b) * NSEQ;
    #pragma unroll
    for (int mt = 0; mt < 2; ++mt)
        #pragma unroll
        for (int nt = 0; nt < 4; ++nt) {
            int trow = t0 + wm * 32 + mt * 16 + g;
            int nl   = wn * 32 + nt * 8 + t2;
            float* dst = (nl < 64) ? g_pnum : g_pden;
            int d = d0 + ((nl < 64) ? nl : nl - 64);
            size_t base = (pbase + trow) * DIM + d;
            *reinterpret_cast<float2*>(&dst[base]) =
                make_float2(acc[mt][nt][0], acc[mt][nt][1]);
            *reinterpret_cast<float2*>(&dst[base + 8 * DIM]) =
                make_float2(acc[mt][nt][2], acc[mt][nt][3]);
        }

    // ---- fused finalize: last arriving K-split block sums + writes out ----
    __threadfence();
    if (tid == 0) {
        int old = atomicAdd(&g_ctr[bx >> 2], 1);
        s_last = (old == KSPLIT - 1) ? 1 : 0;
        if (old == KSPLIT - 1) g_ctr[bx >> 2] = 0;   // reset for next replay
    }
    __syncthreads();
    if (s_last) {
        // tile: rows t0..t0+63, cols d0..d0+63 (16 float4 per row)
        for (int it = tid; it < 64 * 16; it += 256) {
            int trow = t0 + (it >> 4);
            int dc4  = (d0 >> 2) + (it & 15);
            float4 n = make_float4(0.f, 0.f, 0.f, 0.f);
            float4 dn = make_float4(0.f, 0.f, 0.f, 0.f);
            #pragma unroll
            for (int s = 0; s < KSPLIT; ++s) {
                size_t pi = ((size_t)(s * BSZ + b) * NSEQ + trow) * (DIM / 4) + dc4;
                float4 pn = reinterpret_cast<const float4*>(g_pnum)[pi];
                float4 pd = reinterpret_cast<const float4*>(g_pden)[pi];
                n.x += pn.x; n.y += pn.y; n.z += pn.z; n.w += pn.w;
                dn.x += pd.x; dn.y += pd.y; dn.z += pd.z; dn.w += pd.w;
            }
            size_t gi = ((size_t)(b * NSEQ) + trow) * (DIM / 4) + dc4;
            float4 q = reinterpret_cast<const float4*>(g_q)[gi];
            reinterpret_cast<float4*>(out)[gi] = make_float4(
                q.x * (n.x / dn.x), q.y * (n.y / dn.y),
                q.z * (n.z / dn.z), q.w * (n.w / dn.w));
        }
    }
}

// ---------------------------------------------------------------------------
extern "C" void kernel_launch(void* const* d_in, const int* in_sizes, int n_in,
                              void* d_out, int out_size)
{
    const float* x        = (const float*)d_in[0];
    const float* Wq       = (const float*)d_in[1];
    const float* bq       = (const float*)d_in[2];
    const float* Wk       = (const float*)d_in[3];
    const float* bk       = (const float*)d_in[4];
    const float* Wv       = (const float*)d_in[5];
    const float* bv       = (const float*)d_in[6];
    const float* pos_bias = (const float*)d_in[7];
    float* out = (float*)d_out;

    cudaFuncSetAttribute(aft_mma_kernel,
                         cudaFuncAttributeMaxDynamicSharedMemorySize, AFT_SMEM);

    prep_inputs_kernel<<<1120, 256>>>(x, Wq, Wk, Wv, pos_bias);
    proj_mma_kernel<<<dim3(6, 32), 256>>>(bq, bk, bv);
    prep_t_kernel<<<256, 256>>>();
    aft_mma_kernel<<<256, 256, AFT_SMEM>>>(out);
}

// round 17
// speedup vs baseline: 1.0548x; 1.0548x over previous
#include <cuda_runtime.h>
#include <cuda_bf16.h>
#include <math.h>
#include <stdint.h>

#define BSZ  4
#define NSEQ 512
#define DIM  128
#define MROWS (BSZ * NSEQ)      // 2048
#define KSPLIT 4

// ---- scratch (__device__ globals; no cudaMalloc allowed) -------------------
__device__ float g_q   [MROWS * DIM];
__device__ float g_ek  [MROWS * DIM];
__device__ float g_vraw[MROWS * DIM];
__device__ float g_pnum[KSPLIT * MROWS * DIM];
__device__ float g_pden[KSPLIT * MROWS * DIM];

// bf16 hi/lo split operands
__device__ uint4 g_xh   [MROWS * DIM / 8];
__device__ uint4 g_xl   [MROWS * DIM / 8];
__device__ uint4 g_wch  [3 * DIM * DIM / 8];
__device__ uint4 g_wcl  [3 * DIM * DIM / 8];
__device__ uint4 g_wh   [NSEQ * NSEQ / 8];
__device__ uint4 g_wl   [NSEQ * NSEQ / 8];
__device__ uint4 g_ekvTh[BSZ * DIM * NSEQ / 8];
__device__ uint4 g_ekvTl[BSZ * DIM * NSEQ / 8];
__device__ uint4 g_ekTh [BSZ * DIM * NSEQ / 8];
__device__ uint4 g_ekTl [BSZ * DIM * NSEQ / 8];

// ---------------------------------------------------------------------------
__device__ __forceinline__ uint32_t smem_u32(const void* p) {
    uint32_t a;
    asm("{ .reg .u64 t; cvta.to.shared.u64 t, %1; cvt.u32.u64 %0, t; }"
        : "=r"(a) : "l"(p));
    return a;
}
#define LDSM_X4(r0, r1, r2, r3, addr) \
    asm volatile("ldmatrix.sync.aligned.m8n8.x4.shared.b16 {%0,%1,%2,%3}, [%4];" \
        : "=r"(r0), "=r"(r1), "=r"(r2), "=r"(r3) : "r"(addr))

#define MMA16816(d, a, b0, b1) \
    asm volatile("mma.sync.aligned.m16n8k16.row.col.f32.bf16.bf16.f32 " \
        "{%0,%1,%2,%3}, {%4,%5,%6,%7}, {%8,%9}, {%0,%1,%2,%3};" \
        : "+f"((d)[0]), "+f"((d)[1]), "+f"((d)[2]), "+f"((d)[3]) \
        : "r"((a)[0]), "r"((a)[1]), "r"((a)[2]), "r"((a)[3]), \
          "r"(b0), "r"(b1))

__device__ __forceinline__ void cp16(uint32_t saddr, const void* gptr) {
    asm volatile("cp.async.cg.shared.global [%0], [%1], 16;"
                 :: "r"(saddr), "l"(gptr));
}
__device__ __forceinline__ void cp_commit() {
    asm volatile("cp.async.commit_group;" ::: "memory");
}
__device__ __forceinline__ void cp_wait0() {
    asm volatile("cp.async.wait_group 0;" ::: "memory");
}

__device__ __forceinline__ void bsplit(float x, unsigned short& h, unsigned short& l) {
    __nv_bfloat16 hb = __float2bfloat16(x);
    __nv_bfloat16 lb = __float2bfloat16(x - __bfloat162float(hb));
    h = __bfloat16_as_ushort(hb);
    l = __bfloat16_as_ushort(lb);
}

// geometry
#define RSTRIDE 80
#define PSA_HI 0
#define PSA_LO 5120
#define PSB_HI 10240
#define PSB_LO 15360
#define PBUFSZ 20480
#define ASA_HI 0
#define ASA_LO 5120
#define ASB_HI 10240
#define ASB_LO 20480
#define ABUFSZ 30720
#define AFT_SMEM (2 * ABUFSZ)   // 61440

// ---------------------------------------------------------------------------
// Kernel 0: merged input prep — x split, Wcat split, exp(pos_bias) split.
// items: x 131072 + Wcat 24576 + pos_bias 131072 = 286720 float2 -> 1120 blks
// ---------------------------------------------------------------------------
__global__ __launch_bounds__(256)
void prep_inputs_kernel(const float* __restrict__ x,
                        const float* __restrict__ Wq,
                        const float* __restrict__ Wk,
                        const float* __restrict__ Wv,
                        const float* __restrict__ pos_bias)
{
    int i = blockIdx.x * 256 + threadIdx.x;
    if (i < MROWS * DIM / 2) {                       // x
        float2 p = reinterpret_cast<const float2*>(x)[i];
        unsigned short h0, l0, h1, l1;
        bsplit(p.x, h0, l0); bsplit(p.y, h1, l1);
        reinterpret_cast<uint32_t*>(g_xh)[i] = ((uint32_t)h1 << 16) | h0;
        reinterpret_cast<uint32_t*>(g_xl)[i] = ((uint32_t)l1 << 16) | l0;
    } else if (i < MROWS * DIM / 2 + 3 * DIM * DIM / 2) {   // Wcat
        int j = i - MROWS * DIM / 2;
        int row = j >> 6, c2 = j & 63;
        int m = row >> 7, rr = row & 127;
        const float* W = (m == 0) ? Wq : (m == 1) ? Wk : Wv;
        float2 p = reinterpret_cast<const float2*>(W + rr * DIM)[c2];
        unsigned short h0, l0, h1, l1;
        bsplit(p.x, h0, l0); bsplit(p.y, h1, l1);
        reinterpret_cast<uint32_t*>(g_wch)[j] = ((uint32_t)h1 << 16) | h0;
        reinterpret_cast<uint32_t*>(g_wcl)[j] = ((uint32_t)l1 << 16) | l0;
    } else {                                          // exp(pos_bias)
        int j = i - (MROWS * DIM / 2 + 3 * DIM * DIM / 2);
        float2 p = reinterpret_cast<const float2*>(pos_bias)[j];
        float e0 = __expf(p.x), e1 = __expf(p.y);
        unsigned short h0, l0, h1, l1;
        bsplit(e0, h0, l0); bsplit(e1, h1, l1);
        reinterpret_cast<uint32_t*>(g_wh)[j] = ((uint32_t)h1 << 16) | h0;
        reinterpret_cast<uint32_t*>(g_wl)[j] = ((uint32_t)l1 << 16) | l0;
    }
}

// ---------------------------------------------------------------------------
// Kernel 1: projections on mma.sync (__expf epilogue)
// ---------------------------------------------------------------------------
__global__ __launch_bounds__(256)
void proj_mma_kernel(const float* __restrict__ bq,
                     const float* __restrict__ bk,
                     const float* __restrict__ bv)
{
    __shared__ __align__(16) char sm[2 * PBUFSZ];
    const uint32_t smem = smem_u32(sm);

    const int tid  = threadIdx.x;
    const int wid  = tid >> 5, lane = tid & 31;
    const int et   = blockIdx.x;
    const int rt   = blockIdx.y;
    const int m    = et >> 1;
    const int r0   = rt * 64;
    const int e0   = et * 64;

    const float* __restrict__ bias = (m == 0) ? bq : (m == 1) ? bk : bv;
    float* __restrict__ outp       = (m == 0) ? g_q : (m == 1) ? g_ek : g_vraw;

    const int srow = tid >> 2, sseg = tid & 3;
    const uint32_t soff = (uint32_t)(srow * RSTRIDE + sseg * 16);
    const int a_g = (r0 + srow) * 16 + sseg;
    const int b_g = (e0 + srow) * 16 + sseg;

    const int wm = wid & 1, wn = wid >> 1;
    const int r  = lane & 7, sel = lane >> 3;

    uint32_t aoff[2][2], boff[2];
    #pragma unroll
    for (int mt = 0; mt < 2; ++mt)
        #pragma unroll
        for (int ks = 0; ks < 2; ++ks) {
            int row = wm * 32 + mt * 16 + r + (sel & 1) * 8;
            aoff[mt][ks] = smem + PSA_HI + row * RSTRIDE + ((sel >> 1) * 16) + ks * 32;
        }
    #pragma unroll
    for (int ks = 0; ks < 2; ++ks) {
        int row = wn * 16 + r + (sel >> 1) * 8;
        boff[ks] = smem + PSB_HI + row * RSTRIDE + ((sel & 1) * 16) + ks * 32;
    }

    float acc[2][2][4] = {};

    uint4 pAh = g_xh[a_g], pAl = g_xl[a_g], pBh = g_wch[b_g], pBl = g_wcl[b_g];
    *reinterpret_cast<uint4*>(sm + PSA_HI + soff) = pAh;
    *reinterpret_cast<uint4*>(sm + PSA_LO + soff) = pAl;
    *reinterpret_cast<uint4*>(sm + PSB_HI + soff) = pBh;
    *reinterpret_cast<uint4*>(sm + PSB_LO + soff) = pBl;
    __syncthreads();

    for (int c = 0; c < 4; ++c) {
        const uint32_t bo = (uint32_t)(c & 1) * PBUFSZ;
        if (c < 3) {
            int gi = (c + 1) * 4;
            pAh = g_xh[a_g + gi];  pAl = g_xl[a_g + gi];
            pBh = g_wch[b_g + gi]; pBl = g_wcl[b_g + gi];
        }
        #pragma unroll
        for (int ks = 0; ks < 2; ++ks) {
            uint32_t aH[2][4], aL[2][4], bH[4], bL[4];
            LDSM_X4(aH[0][0], aH[0][1], aH[0][2], aH[0][3], aoff[0][ks] + bo);
            LDSM_X4(aH[1][0], aH[1][1], aH[1][2], aH[1][3], aoff[1][ks] + bo);
            LDSM_X4(aL[0][0], aL[0][1], aL[0][2], aL[0][3], aoff[0][ks] + bo + PSA_LO);
            LDSM_X4(aL[1][0], aL[1][1], aL[1][2], aL[1][3], aoff[1][ks] + bo + PSA_LO);
            LDSM_X4(bH[0], bH[1], bH[2], bH[3], boff[ks] + bo);
            LDSM_X4(bL[0], bL[1], bL[2], bL[3], boff[ks] + bo + PSA_LO);
            #pragma unroll
            for (int mt = 0; mt < 2; ++mt)
                #pragma unroll
                for (int nt = 0; nt < 2; ++nt) {
                    MMA16816(acc[mt][nt], aH[mt], bH[nt * 2], bH[nt * 2 + 1]);
                    MMA16816(acc[mt][nt], aH[mt], bL[nt * 2], bL[nt * 2 + 1]);
                    MMA16816(acc[mt][nt], aL[mt], bH[nt * 2], bH[nt * 2 + 1]);
                }
        }
        if (c < 3) {
            const uint32_t nb = (uint32_t)((c + 1) & 1) * PBUFSZ;
            *reinterpret_cast<uint4*>(sm + nb + PSA_HI + soff) = pAh;
            *reinterpret_cast<uint4*>(sm + nb + PSA_LO + soff) = pAl;
            *reinterpret_cast<uint4*>(sm + nb + PSB_HI + soff) = pBh;
            *reinterpret_cast<uint4*>(sm + nb + PSB_LO + soff) = pBl;
        }
        __syncthreads();
    }

    const int g  = lane >> 2;
    const int t2 = (lane & 3) * 2;
    #pragma unroll
    for (int mt = 0; mt < 2; ++mt)
        #pragma unroll
        for (int nt = 0; nt < 2; ++nt) {
            int trow = r0 + wm * 32 + mt * 16 + g;
            int ew   = (et & 1) * 64 + wn * 16 + nt * 8 + t2;
            float b0 = bias[ew], b1 = bias[ew + 1];
            #pragma unroll
            for (int hh = 0; hh < 2; ++hh) {
                float v0 = acc[mt][nt][hh * 2 + 0] + b0;
                float v1 = acc[mt][nt][hh * 2 + 1] + b1;
                if (m == 0)      { v0 = 1.0f / (1.0f + __expf(-v0)); v1 = 1.0f / (1.0f + __expf(-v1)); }
                else if (m == 1) { v0 = __expf(v0); v1 = __expf(v1); }
                *reinterpret_cast<float2*>(&outp[(size_t)(trow + hh * 8) * DIM + ew]) =
                    make_float2(v0, v1);
            }
        }
}

// ---------------------------------------------------------------------------
// Kernel 2: transpose-split ek/ekv -> [b][d][j] bf16 hi/lo. 256 blocks.
// ---------------------------------------------------------------------------
__global__ __launch_bounds__(256)
void prep_t_kernel()
{
    __shared__ float s_ek[32][33], s_v[32][33];
    const int tid = threadIdx.x;
    const int bx = blockIdx.x;
    const int jt = bx & 15, dt = (bx >> 4) & 3, b = bx >> 6;
    const int j0 = jt * 32, d0 = dt * 32;

    const float* __restrict__ ekp = g_ek   + b * NSEQ * DIM;
    const float* __restrict__ vp  = g_vraw + b * NSEQ * DIM;

    for (int i = tid; i < 1024; i += 256) {
        int jj = i >> 5, dd = i & 31;
        s_ek[jj][dd] = ekp[(j0 + jj) * DIM + d0 + dd];
        s_v [jj][dd] = vp [(j0 + jj) * DIM + d0 + dd];
    }
    __syncthreads();

    for (int i = tid; i < 512; i += 256) {
        int dd = i >> 4, jj = (i & 15) * 2;
        float ek0 = s_ek[jj][dd],     ek1 = s_ek[jj + 1][dd];
        float v0  = s_v [jj][dd],     v1  = s_v [jj + 1][dd];
        float ekv0 = ek0 * v0, ekv1 = ek1 * v1;
        unsigned short kh0, kl0, kh1, kl1, vh0, vl0, vh1, vl1;
        bsplit(ek0,  kh0, kl0);  bsplit(ek1,  kh1, kl1);
        bsplit(ekv0, vh0, vl0);  bsplit(ekv1, vh1, vl1);
        uint32_t u32i = (((b * DIM + d0 + dd) * NSEQ) + j0 + jj) >> 1;
        reinterpret_cast<uint32_t*>(g_ekTh )[u32i] = ((uint32_t)kh1 << 16) | kh0;
        reinterpret_cast<uint32_t*>(g_ekTl )[u32i] = ((uint32_t)kl1 << 16) | kl0;
        reinterpret_cast<uint32_t*>(g_ekvTh)[u32i] = ((uint32_t)vh1 << 16) | vh0;
        reinterpret_cast<uint32_t*>(g_ekvTl)[u32i] = ((uint32_t)vl1 << 16) | vl0;
    }
}

// ---------------------------------------------------------------------------
// Kernel 3: AFT core — R13 mainloop (no fused finalize; partials only).
// Block tile 64t x 128n, K=128 in 4 chunks, cp.async double buffer.
// Grid 256 = ksl(4) x b(4) x tt(8) x dh(2).
// ---------------------------------------------------------------------------
__global__ __launch_bounds__(256)
void aft_mma_kernel()
{
    extern __shared__ __align__(16) char sm[];
    const uint32_t smem = smem_u32(sm);

    const int tid  = threadIdx.x;
    const int wid  = tid >> 5, lane = tid & 31;
    const int bx   = blockIdx.x;
    const int ksl  = bx & 3;
    const int b    = (bx >> 2) & 3;
    const int tt   = (bx >> 4) & 7;
    const int dh   = (bx >> 7) & 1;
    const int t0   = tt * 64;
    const int d0   = dh * 64;
    const int j0u4 = ksl * 16;

    const uint4* srcH[3];
    const uint4* srcL[3];
    uint32_t shOff[3], slOff[3];
    int gb[3];
    #pragma unroll
    for (int k = 0; k < 3; ++k) {
        int i = tid + k * 256;
        int row = i >> 2, seg = i & 3;
        if (row < 64) {
            srcH[k] = g_wh;  srcL[k] = g_wl;
            shOff[k] = ASA_HI + row * RSTRIDE + seg * 16;
            slOff[k] = ASA_LO + row * RSTRIDE + seg * 16;
            gb[k] = (t0 + row) * 64 + j0u4 + seg;
        } else {
            int n = row - 64;
            shOff[k] = ASB_HI + n * RSTRIDE + seg * 16;
            slOff[k] = ASB_LO + n * RSTRIDE + seg * 16;
            int dcol = (n < 64) ? (d0 + n) : (d0 + n - 64);
            srcH[k] = (n < 64) ? g_ekvTh : g_ekTh;
            srcL[k] = (n < 64) ? g_ekvTl : g_ekTl;
            gb[k] = (b * DIM + dcol) * 64 + j0u4 + seg;
        }
    }

    const int wm = wid & 1, wn = wid >> 1;
    const int r  = lane & 7, sel = lane >> 3;

    uint32_t aoff[2][2], boff[2][2];
    #pragma unroll
    for (int mt = 0; mt < 2; ++mt)
        #pragma unroll
        for (int ks = 0; ks < 2; ++ks) {
            int row = wm * 32 + mt * 16 + r + (sel & 1) * 8;
            aoff[mt][ks] = smem + ASA_HI + row * RSTRIDE + ((sel >> 1) * 16) + ks * 32;
        }
    #pragma unroll
    for (int ng = 0; ng < 2; ++ng)
        #pragma unroll
        for (int ks = 0; ks < 2; ++ks) {
            int row = wn * 32 + ng * 16 + r + (sel >> 1) * 8;
            boff[ng][ks] = smem + ASB_HI + row * RSTRIDE + ((sel & 1) * 16) + ks * 32;
        }

    float acc[2][4][4] = {};

    #pragma unroll
    for (int k = 0; k < 3; ++k) {
        cp16(smem + shOff[k], srcH[k] + gb[k]);
        cp16(smem + slOff[k], srcL[k] + gb[k]);
    }
    cp_commit();
    cp_wait0();
    __syncthreads();

    for (int c = 0; c < 4; ++c) {
        const uint32_t bo = (uint32_t)(c & 1) * ABUFSZ;
        if (c < 3) {
            const uint32_t nb = (uint32_t)((c + 1) & 1) * ABUFSZ;
            int gi = (c + 1) * 4;
            #pragma unroll
            for (int k = 0; k < 3; ++k) {
                cp16(smem + nb + shOff[k], srcH[k] + gb[k] + gi);
                cp16(smem + nb + slOff[k], srcL[k] + gb[k] + gi);
            }
            cp_commit();
        }

        #pragma unroll
        for (int ks = 0; ks < 2; ++ks) {
            uint32_t aH[2][4], aL[2][4], bH[2][4], bL[2][4];
            LDSM_X4(aH[0][0], aH[0][1], aH[0][2], aH[0][3], aoff[0][ks] + bo);
            LDSM_X4(aH[1][0], aH[1][1], aH[1][2], aH[1][3], aoff[1][ks] + bo);
            LDSM_X4(aL[0][0], aL[0][1], aL[0][2], aL[0][3], aoff[0][ks] + bo + 5120);
            LDSM_X4(aL[1][0], aL[1][1], aL[1][2], aL[1][3], aoff[1][ks] + bo + 5120);
            LDSM_X4(bH[0][0], bH[0][1], bH[0][2], bH[0][3], boff[0][ks] + bo);
            LDSM_X4(bH[1][0], bH[1][1], bH[1][2], bH[1][3], boff[1][ks] + bo);
            LDSM_X4(bL[0][0], bL[0][1], bL[0][2], bL[0][3], boff[0][ks] + bo + 10240);
            LDSM_X4(bL[1][0], bL[1][1], bL[1][2], bL[1][3], boff[1][ks] + bo + 10240);

            #pragma unroll
            for (int mt = 0; mt < 2; ++mt)
                #pragma unroll
                for (int ng = 0; ng < 2; ++ng)
                    #pragma unroll
                    for (int sub = 0; sub < 2; ++sub) {
                        int nt = ng * 2 + sub;
                        MMA16816(acc[mt][nt], aH[mt], bH[ng][sub * 2], bH[ng][sub * 2 + 1]);
                        MMA16816(acc[mt][nt], aH[mt], bL[ng][sub * 2], bL[ng][sub * 2 + 1]);
                        MMA16816(acc[mt][nt], aL[mt], bH[ng][sub * 2], bH[ng][sub * 2 + 1]);
                    }
        }
        cp_wait0();
        __syncthreads();
    }

    // ---- write partials ----
    const int g  = lane >> 2;
    const int t2 = (lane & 3) * 2;
    const size_t pbase = (size_t)(ksl * BSZ + b) * NSEQ;
    #pragma unroll
    for (int mt = 0; mt < 2; ++mt)
        #pragma unroll
        for (int nt = 0; nt < 4; ++nt) {
            int trow = t0 + wm * 32 + mt * 16 + g;
            int nl   = wn * 32 + nt * 8 + t2;
            float* dst = (nl < 64) ? g_pnum : g_pden;
            int d = d0 + ((nl < 64) ? nl : nl - 64);
            size_t base = (pbase + trow) * DIM + d;
            *reinterpret_cast<float2*>(&dst[base]) =
                make_float2(acc[mt][nt][0], acc[mt][nt][1]);
            *reinterpret_cast<float2*>(&dst[base + 8 * DIM]) =
                make_float2(acc[mt][nt][2], acc[mt][nt][3]);
        }
}

// ---------------------------------------------------------------------------
// Kernel 4: finalize — out = q * (sum_ksl pnum) / (sum_ksl pden)
// ---------------------------------------------------------------------------
__global__ __launch_bounds__(256)
void finalize_kernel(float* __restrict__ out)
{
    int i = blockIdx.x * 256 + threadIdx.x;     // 65536 float4
    const int STRIDE = MROWS * DIM / 4;
    float4 n = make_float4(0.f, 0.f, 0.f, 0.f);
    float4 d = make_float4(0.f, 0.f, 0.f, 0.f);
    #pragma unroll
    for (int s = 0; s < KSPLIT; ++s) {
        float4 pn = reinterpret_cast<const float4*>(g_pnum)[s * STRIDE + i];
        float4 pd = reinterpret_cast<const float4*>(g_pden)[s * STRIDE + i];
        n.x += pn.x; n.y += pn.y; n.z += pn.z; n.w += pn.w;
        d.x += pd.x; d.y += pd.y; d.z += pd.z; d.w += pd.w;
    }
    float4 q = reinterpret_cast<const float4*>(g_q)[i];
    reinterpret_cast<float4*>(out)[i] = make_float4(
        q.x * (n.x / d.x), q.y * (n.y / d.y),
        q.z * (n.z / d.z), q.w * (n.w / d.w));
}

// ---------------------------------------------------------------------------
extern "C" void kernel_launch(void* const* d_in, const int* in_sizes, int n_in,
                              void* d_out, int out_size)
{
    const float* x        = (const float*)d_in[0];
    const float* Wq       = (const float*)d_in[1];
    const float* bq       = (const float*)d_in[2];
    const float* Wk       = (const float*)d_in[3];
    const float* bk       = (const float*)d_in[4];
    const float* Wv       = (const float*)d_in[5];
    const float* bv       = (const float*)d_in[6];
    const float* pos_bias = (const float*)d_in[7];
    float* out = (float*)d_out;

    cudaFuncSetAttribute(aft_mma_kernel,
                         cudaFuncAttributeMaxDynamicSharedMemorySize, AFT_SMEM);

    prep_inputs_kernel<<<1120, 256>>>(x, Wq, Wk, Wv, pos_bias);
    proj_mma_kernel<<<dim3(6, 32), 256>>>(bq, bk, bv);
    prep_t_kernel<<<256, 256>>>();
    aft_mma_kernel<<<256, 256, AFT_SMEM>>>();
    finalize_kernel<<<256, 256>>>(out);
}